// round 4
// baseline (speedup 1.0000x reference)
#include <cuda_runtime.h>
#include <cuda_bf16.h>
#include <cstdint>

// Problem constants (fixed by the reference generator)
#define NNODES 100000
#define DIM    128          // FAC_K * DIM_K = 4 * 32
#define FAC_K  4
#define DIM_K  32

// Scratch: node-major factor embeddings. fac[n*128 + f*32 + k]
__device__ float g_fac[(size_t)NNODES * DIM];
__device__ float g_new[(size_t)NNODES * DIM];
__device__ float g_agg[(size_t)NNODES * DIM];

// ---------------------------------------------------------------------------
// vector red: red.global.add.v4.f32 (sm_90+)
// ---------------------------------------------------------------------------
__device__ __forceinline__ void red_add_v4(float* addr, float x, float y, float z, float w) {
    asm volatile("red.global.add.v4.f32 [%0], {%1, %2, %3, %4};"
                 :: "l"(addr), "f"(x), "f"(y), "f"(z), "f"(w)
                 : "memory");
}

// ---------------------------------------------------------------------------
// GEMM + leakyReLU + per-factor L2 norm.
// W' = W + b held in smem (128x128 f32). 64-row A tiles in smem.
// 8 warps/block; warp handles 8 rows; lane computes 4 contiguous cols.
// Output node-major: fac[n*128 + c].
// ---------------------------------------------------------------------------
__global__ void __launch_bounds__(256, 2)
gemm_kernel(const float* __restrict__ emb, const float* __restrict__ W,
            const float* __restrict__ b, float* __restrict__ fac) {
    extern __shared__ float sm[];
    float* sW = sm;               // 128*128 floats
    float* sA = sm + DIM * DIM;   // 64*128 floats

    const int tid  = threadIdx.x;
    const int lane = tid & 31;
    const int w    = tid >> 5;

    // Build W'[d][c] = W[f][d][k] + b[f][k],  c = f*32+k
    for (int i = tid; i < DIM * DIM; i += 256) {
        int d = i >> 7, c = i & 127;
        int f = c >> 5, k = c & 31;
        sW[i] = W[(f * DIM + d) * DIM_K + k] + b[f * DIM_K + k];
    }
    __syncthreads();

    const float4* sW4 = (const float4*)sW;
    const int TILE = 64;

    for (int base = blockIdx.x * TILE; base < NNODES; base += gridDim.x * TILE) {
        int rows = NNODES - base; if (rows > TILE) rows = TILE;
        __syncthreads();
        // stage A tile (rows x 128) as float4
        const float4* src = (const float4*)(emb + (size_t)base * DIM);
        float4* dstA = (float4*)sA;
        for (int i = tid; i < rows * (DIM / 4); i += 256) dstA[i] = src[i];
        __syncthreads();

        float4 acc[8];
        #pragma unroll
        for (int r = 0; r < 8; r++) acc[r] = make_float4(0.f, 0.f, 0.f, 0.f);

        #pragma unroll 4
        for (int d = 0; d < DIM; d++) {
            float4 w4 = sW4[d * 32 + lane];
            #pragma unroll
            for (int r = 0; r < 8; r++) {
                float a = sA[(w * 8 + r) * DIM + d];  // broadcast
                acc[r].x += a * w4.x; acc[r].y += a * w4.y;
                acc[r].z += a * w4.z; acc[r].w += a * w4.w;
            }
        }

        #pragma unroll
        for (int r = 0; r < 8; r++) {
            int gr = base + w * 8 + r;
            if (gr >= NNODES) break;   // uniform across warp
            float4 v = acc[r];
            v.x = v.x > 0.f ? v.x : 0.2f * v.x;
            v.y = v.y > 0.f ? v.y : 0.2f * v.y;
            v.z = v.z > 0.f ? v.z : 0.2f * v.z;
            v.w = v.w > 0.f ? v.w : 0.2f * v.w;
            float s = v.x*v.x + v.y*v.y + v.z*v.z + v.w*v.w;
            s += __shfl_xor_sync(0xFFFFFFFFu, s, 1);
            s += __shfl_xor_sync(0xFFFFFFFFu, s, 2);
            s += __shfl_xor_sync(0xFFFFFFFFu, s, 4);   // 8-lane group = one factor
            float inv = 1.0f / fmaxf(sqrtf(s), 1e-12f);
            v.x *= inv; v.y *= inv; v.z *= inv; v.w *= inv;
            ((float4*)(fac + (size_t)gr * DIM))[lane] = v;
        }
    }
}

// ---------------------------------------------------------------------------
// Edge propagation: one warp per edge.
// lane l holds elements [4l,4l+3]; factor f = l/8.
// dot per factor via xor-1/2/4 reduce; softmax across 4 factors via xor-8/16.
// scatter p*tail into agg[row] via red.global.add.v4.
// ---------------------------------------------------------------------------
__global__ void __launch_bounds__(256)
edge_kernel(const float* __restrict__ head_src, const float* __restrict__ tail_src,
            const int* __restrict__ row, const int* __restrict__ col,
            float* __restrict__ agg, int E) {
    const int lane   = threadIdx.x & 31;
    const int warp   = blockIdx.x * (blockDim.x >> 5) + (threadIdx.x >> 5);
    const int nwarps = gridDim.x * (blockDim.x >> 5);

    for (int e = warp; e < E; e += nwarps) {
        int r = __ldg(row + e);
        int c = __ldg(col + e);
        float4 h = __ldg((const float4*)(head_src + (size_t)r * DIM) + lane);
        float4 t = __ldg((const float4*)(tail_src + (size_t)c * DIM) + lane);
        float dp = h.x*t.x + h.y*t.y + h.z*t.z + h.w*t.w;
        dp += __shfl_xor_sync(0xFFFFFFFFu, dp, 1);
        dp += __shfl_xor_sync(0xFFFFFFFFu, dp, 2);
        dp += __shfl_xor_sync(0xFFFFFFFFu, dp, 4);
        float a  = dp;                                   // own factor's dot
        float bv = __shfl_xor_sync(0xFFFFFFFFu, a, 8);
        float cv = __shfl_xor_sync(0xFFFFFFFFu, a, 16);
        float dv = __shfl_xor_sync(0xFFFFFFFFu, bv, 16);
        float m  = fmaxf(fmaxf(a, bv), fmaxf(cv, dv));
        float ea = __expf(a - m);
        float s  = ea + __expf(bv - m) + __expf(cv - m) + __expf(dv - m);
        float p  = ea / s;
        float* dst = agg + (size_t)r * DIM + lane * 4;
        red_add_v4(dst, p * t.x, p * t.y, p * t.z, p * t.w);
    }
}

// ---------------------------------------------------------------------------
// new = l2norm(fac + agg) per (node, factor). Optionally clears agg in-pass.
// One warp per node.
// ---------------------------------------------------------------------------
__global__ void __launch_bounds__(256)
norm_kernel(const float* __restrict__ fac, float* __restrict__ agg,
            float* __restrict__ out, int clear) {
    const int lane   = threadIdx.x & 31;
    const int warp   = blockIdx.x * (blockDim.x >> 5) + (threadIdx.x >> 5);
    const int nwarps = gridDim.x * (blockDim.x >> 5);

    for (int n = warp; n < NNODES; n += nwarps) {
        size_t off = (size_t)n * DIM + lane * 4;
        float4 f = *(const float4*)(fac + off);
        float4 g = *(const float4*)(agg + off);
        if (clear) *(float4*)(agg + off) = make_float4(0.f, 0.f, 0.f, 0.f);
        float4 v = make_float4(f.x + g.x, f.y + g.y, f.z + g.z, f.w + g.w);
        float s = v.x*v.x + v.y*v.y + v.z*v.z + v.w*v.w;
        s += __shfl_xor_sync(0xFFFFFFFFu, s, 1);
        s += __shfl_xor_sync(0xFFFFFFFFu, s, 2);
        s += __shfl_xor_sync(0xFFFFFFFFu, s, 4);
        float inv = 1.0f / fmaxf(sqrtf(s), 1e-12f);
        v.x *= inv; v.y *= inv; v.z *= inv; v.w *= inv;
        *(float4*)(out + off) = v;
    }
}

__global__ void zero_kernel(float* __restrict__ agg) {
    size_t i = (size_t)blockIdx.x * blockDim.x + threadIdx.x;
    size_t total = (size_t)NNODES * DIM / 4;
    float4* a4 = (float4*)agg;
    for (; i < total; i += (size_t)gridDim.x * blockDim.x)
        a4[i] = make_float4(0.f, 0.f, 0.f, 0.f);
}

// ---------------------------------------------------------------------------
extern "C" void kernel_launch(void* const* d_in, const int* in_sizes, int n_in,
                              void* d_out, int out_size) {
    const float* all_emb = (const float*)d_in[0];
    const float* W       = (const float*)d_in[1];
    const float* b       = (const float*)d_in[2];
    const int*   row     = (const int*)  d_in[3];
    const int*   col     = (const int*)  d_in[4];
    const int    E       = in_sizes[3];
    float*       out     = (float*)d_out;

    float *fac, *nf, *agg;
    cudaGetSymbolAddress((void**)&fac, g_fac);
    cudaGetSymbolAddress((void**)&nf,  g_new);
    cudaGetSymbolAddress((void**)&agg, g_agg);

    const int smem = (DIM * DIM + 64 * DIM) * sizeof(float);  // 96 KB
    cudaFuncSetAttribute(gemm_kernel, cudaFuncAttributeMaxDynamicSharedMemorySize, smem);

    // Phase 1: factor embeddings
    gemm_kernel<<<1563, 256, smem>>>(all_emb, W, b, fac);

    // Phase 2: iteration 0 (head = fac, tail = fac)
    zero_kernel<<<512, 256>>>(agg);
    edge_kernel<<<2048, 256>>>(fac, fac, row, col, agg, E);
    norm_kernel<<<512, 256>>>(fac, agg, nf, /*clear=*/1);

    // Phase 3: iteration 1 (head = new, tail = fac) -> final output
    edge_kernel<<<2048, 256>>>(nf, fac, row, col, agg, E);
    norm_kernel<<<512, 256>>>(fac, agg, out, /*clear=*/0);
}

// round 8
// speedup vs baseline: 2.0568x; 2.0568x over previous
#include <cuda_runtime.h>
#include <cuda_bf16.h>
#include <cstdint>

// Problem constants (fixed by the reference generator)
#define NNODES 100000
#define DIM    128          // FAC_K * DIM_K = 4 * 32
#define FAC_K  4
#define DIM_K  32
#define EMAX   1600000

// Scratch (node-major: fac[n*128 + f*32 + k])
__device__ float g_fac[(size_t)NNODES * DIM];
__device__ float g_new[(size_t)NNODES * DIM];
__device__ int   g_deg[NNODES];
__device__ int   g_start[NNODES + 1];
__device__ int   g_cursor[NNODES];
__device__ int   g_colS[EMAX];

// ---------------------------------------------------------------------------
// GEMM + leakyReLU + per-factor L2 norm.  (unchanged from R3 — not the bottleneck)
// ---------------------------------------------------------------------------
__global__ void __launch_bounds__(256, 2)
gemm_kernel(const float* __restrict__ emb, const float* __restrict__ W,
            const float* __restrict__ b, float* __restrict__ fac) {
    extern __shared__ float sm[];
    float* sW = sm;               // 128*128 floats
    float* sA = sm + DIM * DIM;   // 64*128 floats

    const int tid  = threadIdx.x;
    const int lane = tid & 31;
    const int w    = tid >> 5;

    // W'[d][c] = W[f][d][k] + b[f][k],  c = f*32+k
    for (int i = tid; i < DIM * DIM; i += 256) {
        int d = i >> 7, c = i & 127;
        int f = c >> 5, k = c & 31;
        sW[i] = W[(f * DIM + d) * DIM_K + k] + b[f * DIM_K + k];
    }
    __syncthreads();

    const float4* sW4 = (const float4*)sW;
    const int TILE = 64;

    for (int base = blockIdx.x * TILE; base < NNODES; base += gridDim.x * TILE) {
        int rows = NNODES - base; if (rows > TILE) rows = TILE;
        __syncthreads();
        const float4* src = (const float4*)(emb + (size_t)base * DIM);
        float4* dstA = (float4*)sA;
        for (int i = tid; i < rows * (DIM / 4); i += 256) dstA[i] = src[i];
        __syncthreads();

        float4 acc[8];
        #pragma unroll
        for (int r = 0; r < 8; r++) acc[r] = make_float4(0.f, 0.f, 0.f, 0.f);

        #pragma unroll 4
        for (int d = 0; d < DIM; d++) {
            float4 w4 = sW4[d * 32 + lane];
            #pragma unroll
            for (int r = 0; r < 8; r++) {
                float a = sA[(w * 8 + r) * DIM + d];
                acc[r].x += a * w4.x; acc[r].y += a * w4.y;
                acc[r].z += a * w4.z; acc[r].w += a * w4.w;
            }
        }

        #pragma unroll
        for (int r = 0; r < 8; r++) {
            int gr = base + w * 8 + r;
            if (gr >= NNODES) break;
            float4 v = acc[r];
            v.x = v.x > 0.f ? v.x : 0.2f * v.x;
            v.y = v.y > 0.f ? v.y : 0.2f * v.y;
            v.z = v.z > 0.f ? v.z : 0.2f * v.z;
            v.w = v.w > 0.f ? v.w : 0.2f * v.w;
            float s = v.x*v.x + v.y*v.y + v.z*v.z + v.w*v.w;
            s += __shfl_xor_sync(0xFFFFFFFFu, s, 1);
            s += __shfl_xor_sync(0xFFFFFFFFu, s, 2);
            s += __shfl_xor_sync(0xFFFFFFFFu, s, 4);   // 8-lane group = one factor
            float inv = 1.0f / fmaxf(sqrtf(s), 1e-12f);
            v.x *= inv; v.y *= inv; v.z *= inv; v.w *= inv;
            ((float4*)(fac + (size_t)gr * DIM))[lane] = v;
        }
    }
}

// ---------------------------------------------------------------------------
// CSR build: histogram -> single-block exclusive scan -> scatter of col ids.
// ---------------------------------------------------------------------------
__global__ void zero_deg_kernel(int* __restrict__ deg) {
    int i = blockIdx.x * blockDim.x + threadIdx.x;
    if (i < NNODES) deg[i] = 0;
}

__global__ void hist_kernel(const int* __restrict__ row, int E, int* __restrict__ deg) {
    for (int e = blockIdx.x * blockDim.x + threadIdx.x; e < E; e += gridDim.x * blockDim.x)
        atomicAdd(&deg[row[e]], 1);
}

__global__ void scan_kernel(const int* __restrict__ deg, int* __restrict__ start,
                            int* __restrict__ cursor) {
    __shared__ int buf[1024];
    __shared__ int carry_s;
    const int tid = threadIdx.x;
    if (tid == 0) carry_s = 0;
    __syncthreads();
    for (int base = 0; base < NNODES; base += 1024) {
        int i = base + tid;
        int x = (i < NNODES) ? deg[i] : 0;
        buf[tid] = x;
        __syncthreads();
        #pragma unroll
        for (int off = 1; off < 1024; off <<= 1) {
            int v = (tid >= off) ? buf[tid - off] : 0;
            __syncthreads();
            buf[tid] += v;
            __syncthreads();
        }
        int incl  = buf[tid];
        int carry = carry_s;
        __syncthreads();                     // everyone read carry before update
        if (tid == 1023) carry_s = carry + incl;
        int excl = incl - x + carry;
        if (i < NNODES) { start[i] = excl; cursor[i] = excl; }
        __syncthreads();                     // carry_s update visible; buf reusable
    }
    if (tid == 0) start[NNODES] = carry_s;
}

__global__ void scatter_kernel(const int* __restrict__ row, const int* __restrict__ col,
                               int E, int* __restrict__ cursor, int* __restrict__ colS) {
    for (int e = blockIdx.x * blockDim.x + threadIdx.x; e < E; e += gridDim.x * blockDim.x) {
        int r = row[e];
        int pos = atomicAdd(&cursor[r], 1);
        colS[pos] = col[e];
    }
}

// ---------------------------------------------------------------------------
// Fused per-iteration kernel: one warp per destination node.
//   h = head_src[n] (registers, loaded once)
//   for each incident edge: gather t = fac[col], 4-factor softmax(dot(h,t)),
//   acc += p*t in registers. Then out[n] = l2norm_perfactor(fac[n] + acc).
// No atomics, no agg array, no separate norm pass.
// ---------------------------------------------------------------------------
__global__ void __launch_bounds__(256)
fused_edge_norm(const float* __restrict__ head_src,
                const float* __restrict__ fac,
                const int* __restrict__ start,
                const int* __restrict__ colS,
                float* __restrict__ out) {
    const int lane = threadIdx.x & 31;
    const int n = (blockIdx.x * blockDim.x + threadIdx.x) >> 5;
    if (n >= NNODES) return;

    const size_t base = (size_t)n * DIM;
    float4 h = __ldg((const float4*)(head_src + base) + lane);
    int s     = __ldg(start + n);
    int e_end = __ldg(start + n + 1);

    float4 acc = make_float4(0.f, 0.f, 0.f, 0.f);

    // software pipeline, depth 1: gather next tail while computing current
    float4 t = make_float4(0.f, 0.f, 0.f, 0.f);
    if (s < e_end) {
        int c = __ldg(colS + s);
        t = __ldg((const float4*)(fac + (size_t)c * DIM) + lane);
    }
    for (int e = s; e < e_end; e++) {
        float4 tc = t;
        if (e + 1 < e_end) {
            int c = __ldg(colS + e + 1);
            t = __ldg((const float4*)(fac + (size_t)c * DIM) + lane);
        }
        // per-factor dot (8-lane groups): lanes [8f,8f+7] hold factor f
        float dp = h.x*tc.x + h.y*tc.y + h.z*tc.z + h.w*tc.w;
        dp += __shfl_xor_sync(0xFFFFFFFFu, dp, 1);
        dp += __shfl_xor_sync(0xFFFFFFFFu, dp, 2);
        dp += __shfl_xor_sync(0xFFFFFFFFu, dp, 4);
        // dots are in [-1,1] (unit vectors) -> no max-subtraction needed
        float ea = __expf(dp);
        float eb = __shfl_xor_sync(0xFFFFFFFFu, ea, 8);
        float ec = __shfl_xor_sync(0xFFFFFFFFu, ea, 16);
        float ed = __shfl_xor_sync(0xFFFFFFFFu, eb, 16);
        float p  = ea / (ea + eb + ec + ed);
        acc.x += p * tc.x; acc.y += p * tc.y;
        acc.z += p * tc.z; acc.w += p * tc.w;
    }

    // residual base is ALWAYS the original fac (both iterations)
    float4 f = (head_src == fac) ? h : __ldg((const float4*)(fac + base) + lane);
    float4 v = make_float4(f.x + acc.x, f.y + acc.y, f.z + acc.z, f.w + acc.w);
    float ss = v.x*v.x + v.y*v.y + v.z*v.z + v.w*v.w;
    ss += __shfl_xor_sync(0xFFFFFFFFu, ss, 1);
    ss += __shfl_xor_sync(0xFFFFFFFFu, ss, 2);
    ss += __shfl_xor_sync(0xFFFFFFFFu, ss, 4);
    float inv = 1.0f / fmaxf(sqrtf(ss), 1e-12f);
    v.x *= inv; v.y *= inv; v.z *= inv; v.w *= inv;
    ((float4*)(out + base))[lane] = v;
}

// ---------------------------------------------------------------------------
extern "C" void kernel_launch(void* const* d_in, const int* in_sizes, int n_in,
                              void* d_out, int out_size) {
    const float* all_emb = (const float*)d_in[0];
    const float* W       = (const float*)d_in[1];
    const float* b       = (const float*)d_in[2];
    const int*   row     = (const int*)  d_in[3];
    const int*   col     = (const int*)  d_in[4];
    int          E       = in_sizes[3];
    if (E > EMAX) E = EMAX;
    float*       out     = (float*)d_out;

    float *fac, *nf;
    int *deg, *start, *cursor, *colS;
    cudaGetSymbolAddress((void**)&fac,    g_fac);
    cudaGetSymbolAddress((void**)&nf,     g_new);
    cudaGetSymbolAddress((void**)&deg,    g_deg);
    cudaGetSymbolAddress((void**)&start,  g_start);
    cudaGetSymbolAddress((void**)&cursor, g_cursor);
    cudaGetSymbolAddress((void**)&colS,   g_colS);

    const int smem = (DIM * DIM + 64 * DIM) * sizeof(float);  // 96 KB
    cudaFuncSetAttribute(gemm_kernel, cudaFuncAttributeMaxDynamicSharedMemorySize, smem);

    // Phase 1: factor embeddings (overlaps nothing; CSR build is independent
    // of it and runs on the same stream right after)
    gemm_kernel<<<1563, 256, smem>>>(all_emb, W, b, fac);

    // Phase 2: CSR build (row/col identical for both iterations -> build once)
    zero_deg_kernel<<<(NNODES + 255) / 256, 256>>>(deg);
    hist_kernel<<<2048, 256>>>(row, E, deg);
    scan_kernel<<<1, 1024>>>(deg, start, cursor);
    scatter_kernel<<<2048, 256>>>(row, col, E, cursor, colS);

    // Phase 3: two fused propagate+norm iterations (warp per node)
    const int blocks = (NNODES * 32 + 255) / 256;   // 12500
    fused_edge_norm<<<blocks, 256>>>(fac, fac, start, colS, nf);
    fused_edge_norm<<<blocks, 256>>>(nf,  fac, start, colS, out);
}

// round 11
// speedup vs baseline: 2.7468x; 1.3355x over previous
#include <cuda_runtime.h>
#include <cuda_bf16.h>
#include <cstdint>

// Problem constants (fixed by the reference generator)
#define NNODES 100000
#define DIM    128          // FAC_K * DIM_K = 4 * 32
#define FAC_K  4
#define DIM_K  32
#define EMAX   1600000

#define SCAN_CHUNK 2048
#define SCAN_NBLK  ((NNODES + SCAN_CHUNK - 1) / SCAN_CHUNK)   // 49

// Scratch (node-major: fac[n*128 + f*32 + k])
__device__ float g_fac[(size_t)NNODES * DIM];
__device__ float g_new[(size_t)NNODES * DIM];
__device__ int   g_deg[NNODES];
__device__ int   g_start[NNODES + 1];
__device__ int   g_cursor[NNODES];
__device__ int   g_colS[EMAX];
__device__ int   g_bsums[64];
__device__ int   g_boffs[64];

// ---------------------------------------------------------------------------
// GEMM + leakyReLU + per-factor L2 norm.
// ---------------------------------------------------------------------------
__global__ void __launch_bounds__(256, 2)
gemm_kernel(const float* __restrict__ emb, const float* __restrict__ W,
            const float* __restrict__ b, float* __restrict__ fac) {
    extern __shared__ float sm[];
    float* sW = sm;               // 128*128 floats
    float* sA = sm + DIM * DIM;   // 64*128 floats

    const int tid  = threadIdx.x;
    const int lane = tid & 31;
    const int w    = tid >> 5;

    // W'[d][c] = W[f][d][k] + b[f][k],  c = f*32+k
    for (int i = tid; i < DIM * DIM; i += 256) {
        int d = i >> 7, c = i & 127;
        int f = c >> 5, k = c & 31;
        sW[i] = W[(f * DIM + d) * DIM_K + k] + b[f * DIM_K + k];
    }
    __syncthreads();

    const float4* sW4 = (const float4*)sW;
    const int TILE = 64;

    for (int base = blockIdx.x * TILE; base < NNODES; base += gridDim.x * TILE) {
        int rows = NNODES - base; if (rows > TILE) rows = TILE;
        __syncthreads();
        const float4* src = (const float4*)(emb + (size_t)base * DIM);
        float4* dstA = (float4*)sA;
        for (int i = tid; i < rows * (DIM / 4); i += 256) dstA[i] = src[i];
        __syncthreads();

        float4 acc[8];
        #pragma unroll
        for (int r = 0; r < 8; r++) acc[r] = make_float4(0.f, 0.f, 0.f, 0.f);

        #pragma unroll 4
        for (int d = 0; d < DIM; d++) {
            float4 w4 = sW4[d * 32 + lane];
            #pragma unroll
            for (int r = 0; r < 8; r++) {
                float a = sA[(w * 8 + r) * DIM + d];
                acc[r].x += a * w4.x; acc[r].y += a * w4.y;
                acc[r].z += a * w4.z; acc[r].w += a * w4.w;
            }
        }

        #pragma unroll
        for (int r = 0; r < 8; r++) {
            int gr = base + w * 8 + r;
            if (gr >= NNODES) break;
            float4 v = acc[r];
            v.x = v.x > 0.f ? v.x : 0.2f * v.x;
            v.y = v.y > 0.f ? v.y : 0.2f * v.y;
            v.z = v.z > 0.f ? v.z : 0.2f * v.z;
            v.w = v.w > 0.f ? v.w : 0.2f * v.w;
            float s = v.x*v.x + v.y*v.y + v.z*v.z + v.w*v.w;
            s += __shfl_xor_sync(0xFFFFFFFFu, s, 1);
            s += __shfl_xor_sync(0xFFFFFFFFu, s, 2);
            s += __shfl_xor_sync(0xFFFFFFFFu, s, 4);   // 8-lane group = one factor
            float inv = 1.0f / fmaxf(sqrtf(s), 1e-12f);
            v.x *= inv; v.y *= inv; v.z *= inv; v.w *= inv;
            ((float4*)(fac + (size_t)gr * DIM))[lane] = v;
        }
    }
}

// ---------------------------------------------------------------------------
// CSR build: histogram -> 3-phase multi-block scan -> scatter of col ids.
// ---------------------------------------------------------------------------
__global__ void zero_deg_kernel(int* __restrict__ deg) {
    int i = blockIdx.x * blockDim.x + threadIdx.x;
    if (i < NNODES) deg[i] = 0;
}

__global__ void hist_kernel(const int* __restrict__ row, int E, int* __restrict__ deg) {
    for (int e = blockIdx.x * blockDim.x + threadIdx.x; e < E; e += gridDim.x * blockDim.x)
        atomicAdd(&deg[row[e]], 1);
}

// Phase 1: per-block reduction of a 2048-element chunk.
__global__ void __launch_bounds__(256)
scan_partial_kernel(const int* __restrict__ deg, int* __restrict__ bsums) {
    const int tid  = threadIdx.x;
    const int lane = tid & 31;
    const int wid  = tid >> 5;
    const int base = blockIdx.x * SCAN_CHUNK;
    int s = 0;
    #pragma unroll
    for (int k = 0; k < SCAN_CHUNK / 256; k++) {
        int idx = base + tid + k * 256;
        if (idx < NNODES) s += deg[idx];
    }
    s += __shfl_down_sync(0xFFFFFFFFu, s, 16);
    s += __shfl_down_sync(0xFFFFFFFFu, s, 8);
    s += __shfl_down_sync(0xFFFFFFFFu, s, 4);
    s += __shfl_down_sync(0xFFFFFFFFu, s, 2);
    s += __shfl_down_sync(0xFFFFFFFFu, s, 1);
    __shared__ int ws[8];
    if (lane == 0) ws[wid] = s;
    __syncthreads();
    if (wid == 0) {
        int v = (lane < 8) ? ws[lane] : 0;
        v += __shfl_down_sync(0xFFFFFFFFu, v, 4);
        v += __shfl_down_sync(0xFFFFFFFFu, v, 2);
        v += __shfl_down_sync(0xFFFFFFFFu, v, 1);
        if (lane == 0) bsums[blockIdx.x] = v;
    }
}

// Phase 2: exclusive scan of the <=64 block sums; writes total to start[NNODES].
__global__ void scan_sums_kernel(const int* __restrict__ bsums, int* __restrict__ boffs,
                                 int* __restrict__ start) {
    __shared__ int buf[64];
    int tid = threadIdx.x;                         // 64 threads
    int v = (tid < SCAN_NBLK) ? bsums[tid] : 0;
    buf[tid] = v;
    __syncthreads();
    #pragma unroll
    for (int off = 1; off < 64; off <<= 1) {
        int u = (tid >= off) ? buf[tid - off] : 0;
        __syncthreads();
        buf[tid] += u;
        __syncthreads();
    }
    if (tid < SCAN_NBLK) boffs[tid] = buf[tid] - v;   // exclusive
    if (tid == 63) start[NNODES] = buf[63];           // total edge count
}

// Phase 3: per-block re-scan with block offset; writes start + cursor.
__global__ void __launch_bounds__(256)
scan_final_kernel(const int* __restrict__ deg, const int* __restrict__ boffs,
                  int* __restrict__ start, int* __restrict__ cursor) {
    const int tid  = threadIdx.x;
    const int lane = tid & 31;
    const int wid  = tid >> 5;
    const int base = blockIdx.x * SCAN_CHUNK + tid * 8;

    int v[8];
    #pragma unroll
    for (int j = 0; j < 8; j++) {
        int idx = base + j;
        v[j] = (idx < NNODES) ? deg[idx] : 0;
    }
    // thread-local exclusive scan
    int tsum = 0;
    #pragma unroll
    for (int j = 0; j < 8; j++) { int x = v[j]; v[j] = tsum; tsum += x; }

    // warp inclusive scan of thread totals
    int inc = tsum;
    #pragma unroll
    for (int off = 1; off < 32; off <<= 1) {
        int u = __shfl_up_sync(0xFFFFFFFFu, inc, off);
        if (lane >= off) inc += u;
    }
    int wexcl = inc - tsum;

    __shared__ int ws[8], wo[8];
    if (lane == 31) ws[wid] = inc;
    __syncthreads();
    if (tid < 8) {
        int e = 0;
        for (int k = 0; k < tid; k++) e += ws[k];
        wo[tid] = e;
    }
    __syncthreads();

    int off0 = boffs[blockIdx.x] + wo[wid] + wexcl;
    #pragma unroll
    for (int j = 0; j < 8; j++) {
        int idx = base + j;
        if (idx < NNODES) {
            int e = off0 + v[j];
            start[idx]  = e;
            cursor[idx] = e;
        }
    }
}

__global__ void scatter_kernel(const int* __restrict__ row, const int* __restrict__ col,
                               int E, int* __restrict__ cursor, int* __restrict__ colS) {
    for (int e = blockIdx.x * blockDim.x + threadIdx.x; e < E; e += gridDim.x * blockDim.x) {
        int r = row[e];
        int pos = atomicAdd(&cursor[r], 1);
        colS[pos] = col[e];
    }
}

// ---------------------------------------------------------------------------
// Fused per-iteration kernel: one warp per destination node.
// ---------------------------------------------------------------------------
__global__ void __launch_bounds__(256)
fused_edge_norm(const float* __restrict__ head_src,
                const float* __restrict__ fac,
                const int* __restrict__ start,
                const int* __restrict__ colS,
                float* __restrict__ out) {
    const int lane = threadIdx.x & 31;
    const int n = (blockIdx.x * blockDim.x + threadIdx.x) >> 5;
    if (n >= NNODES) return;

    const size_t base = (size_t)n * DIM;
    float4 h = __ldg((const float4*)(head_src + base) + lane);
    int s     = __ldg(start + n);
    int e_end = __ldg(start + n + 1);

    float4 acc = make_float4(0.f, 0.f, 0.f, 0.f);

    // software pipeline, depth 1: gather next tail while computing current
    float4 t = make_float4(0.f, 0.f, 0.f, 0.f);
    if (s < e_end) {
        int c = __ldg(colS + s);
        t = __ldg((const float4*)(fac + (size_t)c * DIM) + lane);
    }
    for (int e = s; e < e_end; e++) {
        float4 tc = t;
        if (e + 1 < e_end) {
            int c = __ldg(colS + e + 1);
            t = __ldg((const float4*)(fac + (size_t)c * DIM) + lane);
        }
        float dp = h.x*tc.x + h.y*tc.y + h.z*tc.z + h.w*tc.w;
        dp += __shfl_xor_sync(0xFFFFFFFFu, dp, 1);
        dp += __shfl_xor_sync(0xFFFFFFFFu, dp, 2);
        dp += __shfl_xor_sync(0xFFFFFFFFu, dp, 4);
        // dots are in [-1,1] (unit vectors) -> no max-subtraction needed
        float ea = __expf(dp);
        float eb = __shfl_xor_sync(0xFFFFFFFFu, ea, 8);
        float ec = __shfl_xor_sync(0xFFFFFFFFu, ea, 16);
        float ed = __shfl_xor_sync(0xFFFFFFFFu, eb, 16);
        float p  = ea / (ea + eb + ec + ed);
        acc.x += p * tc.x; acc.y += p * tc.y;
        acc.z += p * tc.z; acc.w += p * tc.w;
    }

    // residual base is ALWAYS the original fac (both iterations)
    float4 f = (head_src == fac) ? h : __ldg((const float4*)(fac + base) + lane);
    float4 v = make_float4(f.x + acc.x, f.y + acc.y, f.z + acc.z, f.w + acc.w);
    float ss = v.x*v.x + v.y*v.y + v.z*v.z + v.w*v.w;
    ss += __shfl_xor_sync(0xFFFFFFFFu, ss, 1);
    ss += __shfl_xor_sync(0xFFFFFFFFu, ss, 2);
    ss += __shfl_xor_sync(0xFFFFFFFFu, ss, 4);
    float inv = 1.0f / fmaxf(sqrtf(ss), 1e-12f);
    v.x *= inv; v.y *= inv; v.z *= inv; v.w *= inv;
    ((float4*)(out + base))[lane] = v;
}

// ---------------------------------------------------------------------------
extern "C" void kernel_launch(void* const* d_in, const int* in_sizes, int n_in,
                              void* d_out, int out_size) {
    const float* all_emb = (const float*)d_in[0];
    const float* W       = (const float*)d_in[1];
    const float* b       = (const float*)d_in[2];
    const int*   row     = (const int*)  d_in[3];
    const int*   col     = (const int*)  d_in[4];
    int          E       = in_sizes[3];
    if (E > EMAX) E = EMAX;
    float*       out     = (float*)d_out;

    float *fac, *nf;
    int *deg, *start, *cursor, *colS, *bsums, *boffs;
    cudaGetSymbolAddress((void**)&fac,    g_fac);
    cudaGetSymbolAddress((void**)&nf,     g_new);
    cudaGetSymbolAddress((void**)&deg,    g_deg);
    cudaGetSymbolAddress((void**)&start,  g_start);
    cudaGetSymbolAddress((void**)&cursor, g_cursor);
    cudaGetSymbolAddress((void**)&colS,   g_colS);
    cudaGetSymbolAddress((void**)&bsums,  g_bsums);
    cudaGetSymbolAddress((void**)&boffs,  g_boffs);

    const int smem = (DIM * DIM + 64 * DIM) * sizeof(float);  // 96 KB
    cudaFuncSetAttribute(gemm_kernel, cudaFuncAttributeMaxDynamicSharedMemorySize, smem);

    // Phase 1: factor embeddings
    gemm_kernel<<<1563, 256, smem>>>(all_emb, W, b, fac);

    // Phase 2: CSR build (row/col identical for both iterations -> build once)
    zero_deg_kernel<<<(NNODES + 255) / 256, 256>>>(deg);
    hist_kernel<<<2048, 256>>>(row, E, deg);
    scan_partial_kernel<<<SCAN_NBLK, 256>>>(deg, bsums);
    scan_sums_kernel<<<1, 64>>>(bsums, boffs, start);
    scan_final_kernel<<<SCAN_NBLK, 256>>>(deg, boffs, start, cursor);
    scatter_kernel<<<2048, 256>>>(row, col, E, cursor, colS);

    // Phase 3: two fused propagate+norm iterations (warp per node)
    const int blocks = (NNODES * 32 + 255) / 256;   // 12500
    fused_edge_norm<<<blocks, 256>>>(fac, fac, start, colS, nf);
    fused_edge_norm<<<blocks, 256>>>(nf,  fac, start, colS, out);
}

// round 13
// speedup vs baseline: 2.7903x; 1.0159x over previous
#include <cuda_runtime.h>
#include <cuda_fp16.h>
#include <cuda_bf16.h>
#include <cstdint>

// Problem constants (fixed by the reference generator)
#define NNODES 100000
#define DIM    128          // FAC_K * DIM_K = 4 * 32
#define FAC_K  4
#define DIM_K  32
#define EMAX   1600000

#define SCAN_CHUNK 2048
#define SCAN_NBLK  ((NNODES + SCAN_CHUNK - 1) / SCAN_CHUNK)   // 49

// Scratch (node-major: fac[n*128 + f*32 + k])
__device__ float  g_fac[(size_t)NNODES * DIM];
__device__ float  g_new[(size_t)NNODES * DIM];
__device__ __half g_fach[(size_t)NNODES * DIM];   // fp16 copy of fac for gathers
__device__ int    g_deg[NNODES];
__device__ int    g_start[NNODES + 1];
__device__ int    g_cursor[NNODES];
__device__ int    g_colS[EMAX];
__device__ int    g_bsums[64];
__device__ int    g_boffs[64];

// ---------------------------------------------------------------------------
// Blackwell packed fp32 helpers (double-rate FFMA2 — exact fp32 semantics)
// ---------------------------------------------------------------------------
__device__ __forceinline__ unsigned long long pk2(float lo, float hi) {
    unsigned long long r;
    asm("mov.b64 %0, {%1, %2};" : "=l"(r) : "f"(lo), "f"(hi));
    return r;
}
__device__ __forceinline__ void fma2(unsigned long long& d,
                                     unsigned long long a, unsigned long long b) {
    asm("fma.rn.f32x2 %0, %1, %2, %0;" : "+l"(d) : "l"(a), "l"(b));
}
__device__ __forceinline__ void upk2(unsigned long long v, float& lo, float& hi) {
    asm("mov.b64 {%0, %1}, %2;" : "=f"(lo), "=f"(hi) : "l"(v));
}

// ---------------------------------------------------------------------------
// GEMM + leakyReLU + per-factor L2 norm.  fp32x2 packed FMA mainloop.
// Writes fac (fp32) and fac_h (fp16 tail table).
// ---------------------------------------------------------------------------
__global__ void __launch_bounds__(256, 2)
gemm_kernel(const float* __restrict__ emb, const float* __restrict__ W,
            const float* __restrict__ b, float* __restrict__ fac,
            __half* __restrict__ fach) {
    extern __shared__ float sm[];
    float* sW = sm;               // 128*128 floats
    float* sA = sm + DIM * DIM;   // 64*128 floats

    const int tid  = threadIdx.x;
    const int lane = tid & 31;
    const int w    = tid >> 5;

    // W'[d][c] = W[f][d][k] + b[f][k],  c = f*32+k
    for (int i = tid; i < DIM * DIM; i += 256) {
        int d = i >> 7, c = i & 127;
        int f = c >> 5, k = c & 31;
        sW[i] = W[(f * DIM + d) * DIM_K + k] + b[f * DIM_K + k];
    }
    __syncthreads();

    const float4* sW4 = (const float4*)sW;
    const int TILE = 64;

    for (int base = blockIdx.x * TILE; base < NNODES; base += gridDim.x * TILE) {
        int rows = NNODES - base; if (rows > TILE) rows = TILE;
        __syncthreads();
        const float4* src = (const float4*)(emb + (size_t)base * DIM);
        float4* dstA = (float4*)sA;
        for (int i = tid; i < rows * (DIM / 4); i += 256) dstA[i] = src[i];
        __syncthreads();

        unsigned long long axy[8], azw[8];
        #pragma unroll
        for (int r = 0; r < 8; r++) { axy[r] = pk2(0.f, 0.f); azw[r] = pk2(0.f, 0.f); }

        #pragma unroll 2
        for (int d0 = 0; d0 < DIM; d0 += 4) {
            unsigned long long wxy[4], wzw[4];
            #pragma unroll
            for (int i = 0; i < 4; i++) {
                float4 w4 = sW4[(d0 + i) * 32 + lane];
                wxy[i] = pk2(w4.x, w4.y);
                wzw[i] = pk2(w4.z, w4.w);
            }
            #pragma unroll
            for (int r = 0; r < 8; r++) {
                float4 a4 = *(const float4*)&sA[(w * 8 + r) * DIM + d0];
                unsigned long long aa;
                aa = pk2(a4.x, a4.x); fma2(axy[r], aa, wxy[0]); fma2(azw[r], aa, wzw[0]);
                aa = pk2(a4.y, a4.y); fma2(axy[r], aa, wxy[1]); fma2(azw[r], aa, wzw[1]);
                aa = pk2(a4.z, a4.z); fma2(axy[r], aa, wxy[2]); fma2(azw[r], aa, wzw[2]);
                aa = pk2(a4.w, a4.w); fma2(axy[r], aa, wxy[3]); fma2(azw[r], aa, wzw[3]);
            }
        }

        #pragma unroll
        for (int r = 0; r < 8; r++) {
            int gr = base + w * 8 + r;
            if (gr >= NNODES) break;
            float4 v;
            upk2(axy[r], v.x, v.y);
            upk2(azw[r], v.z, v.w);
            v.x = v.x > 0.f ? v.x : 0.2f * v.x;
            v.y = v.y > 0.f ? v.y : 0.2f * v.y;
            v.z = v.z > 0.f ? v.z : 0.2f * v.z;
            v.w = v.w > 0.f ? v.w : 0.2f * v.w;
            float s = v.x*v.x + v.y*v.y + v.z*v.z + v.w*v.w;
            s += __shfl_xor_sync(0xFFFFFFFFu, s, 1);
            s += __shfl_xor_sync(0xFFFFFFFFu, s, 2);
            s += __shfl_xor_sync(0xFFFFFFFFu, s, 4);   // 8-lane group = one factor
            float inv = 1.0f / fmaxf(sqrtf(s), 1e-12f);
            v.x *= inv; v.y *= inv; v.z *= inv; v.w *= inv;
            ((float4*)(fac + (size_t)gr * DIM))[lane] = v;
            // fp16 tail table (components are in [-1,1] after l2norm)
            __half2 h0 = __floats2half2_rn(v.x, v.y);
            __half2 h1 = __floats2half2_rn(v.z, v.w);
            uint2 u;
            u.x = *(unsigned int*)&h0;
            u.y = *(unsigned int*)&h1;
            ((uint2*)fach)[(size_t)gr * 32 + lane] = u;
        }
    }
}

// ---------------------------------------------------------------------------
// CSR build: histogram -> 3-phase multi-block scan -> scatter of col ids.
// ---------------------------------------------------------------------------
__global__ void zero_deg_kernel(int* __restrict__ deg) {
    int i = blockIdx.x * blockDim.x + threadIdx.x;
    if (i < NNODES) deg[i] = 0;
}

__global__ void hist_kernel(const int* __restrict__ row, int E, int* __restrict__ deg) {
    for (int e = blockIdx.x * blockDim.x + threadIdx.x; e < E; e += gridDim.x * blockDim.x)
        atomicAdd(&deg[row[e]], 1);
}

__global__ void __launch_bounds__(256)
scan_partial_kernel(const int* __restrict__ deg, int* __restrict__ bsums) {
    const int tid  = threadIdx.x;
    const int lane = tid & 31;
    const int wid  = tid >> 5;
    const int base = blockIdx.x * SCAN_CHUNK;
    int s = 0;
    #pragma unroll
    for (int k = 0; k < SCAN_CHUNK / 256; k++) {
        int idx = base + tid + k * 256;
        if (idx < NNODES) s += deg[idx];
    }
    s += __shfl_down_sync(0xFFFFFFFFu, s, 16);
    s += __shfl_down_sync(0xFFFFFFFFu, s, 8);
    s += __shfl_down_sync(0xFFFFFFFFu, s, 4);
    s += __shfl_down_sync(0xFFFFFFFFu, s, 2);
    s += __shfl_down_sync(0xFFFFFFFFu, s, 1);
    __shared__ int ws[8];
    if (lane == 0) ws[wid] = s;
    __syncthreads();
    if (wid == 0) {
        int v = (lane < 8) ? ws[lane] : 0;
        v += __shfl_down_sync(0xFFFFFFFFu, v, 4);
        v += __shfl_down_sync(0xFFFFFFFFu, v, 2);
        v += __shfl_down_sync(0xFFFFFFFFu, v, 1);
        if (lane == 0) bsums[blockIdx.x] = v;
    }
}

__global__ void scan_sums_kernel(const int* __restrict__ bsums, int* __restrict__ boffs,
                                 int* __restrict__ start) {
    __shared__ int buf[64];
    int tid = threadIdx.x;                         // 64 threads
    int v = (tid < SCAN_NBLK) ? bsums[tid] : 0;
    buf[tid] = v;
    __syncthreads();
    #pragma unroll
    for (int off = 1; off < 64; off <<= 1) {
        int u = (tid >= off) ? buf[tid - off] : 0;
        __syncthreads();
        buf[tid] += u;
        __syncthreads();
    }
    if (tid < SCAN_NBLK) boffs[tid] = buf[tid] - v;   // exclusive
    if (tid == 63) start[NNODES] = buf[63];           // total edge count
}

__global__ void __launch_bounds__(256)
scan_final_kernel(const int* __restrict__ deg, const int* __restrict__ boffs,
                  int* __restrict__ start, int* __restrict__ cursor) {
    const int tid  = threadIdx.x;
    const int lane = tid & 31;
    const int wid  = tid >> 5;
    const int base = blockIdx.x * SCAN_CHUNK + tid * 8;

    int v[8];
    #pragma unroll
    for (int j = 0; j < 8; j++) {
        int idx = base + j;
        v[j] = (idx < NNODES) ? deg[idx] : 0;
    }
    int tsum = 0;
    #pragma unroll
    for (int j = 0; j < 8; j++) { int x = v[j]; v[j] = tsum; tsum += x; }

    int inc = tsum;
    #pragma unroll
    for (int off = 1; off < 32; off <<= 1) {
        int u = __shfl_up_sync(0xFFFFFFFFu, inc, off);
        if (lane >= off) inc += u;
    }
    int wexcl = inc - tsum;

    __shared__ int ws[8], wo[8];
    if (lane == 31) ws[wid] = inc;
    __syncthreads();
    if (tid < 8) {
        int e = 0;
        for (int k = 0; k < tid; k++) e += ws[k];
        wo[tid] = e;
    }
    __syncthreads();

    int off0 = boffs[blockIdx.x] + wo[wid] + wexcl;
    #pragma unroll
    for (int j = 0; j < 8; j++) {
        int idx = base + j;
        if (idx < NNODES) {
            int e = off0 + v[j];
            start[idx]  = e;
            cursor[idx] = e;
        }
    }
}

__global__ void scatter_kernel(const int* __restrict__ row, const int* __restrict__ col,
                               int E, int* __restrict__ cursor, int* __restrict__ colS) {
    for (int e = blockIdx.x * blockDim.x + threadIdx.x; e < E; e += gridDim.x * blockDim.x) {
        int r = row[e];
        int pos = atomicAdd(&cursor[r], 1);
        colS[pos] = col[e];
    }
}

// ---------------------------------------------------------------------------
// Fused per-iteration kernel: one warp per destination node.
// Head + residual + accumulation + softmax in fp32; tail GATHERS in fp16
// (tails are l2-normalized, components in [-1,1]) -> 256 B/edge instead of 512.
// Depth-2 software pipeline on the tail gather.
// ---------------------------------------------------------------------------
__global__ void __launch_bounds__(256)
fused_edge_norm(const float* __restrict__ head_src,
                const float* __restrict__ fac,
                const __half* __restrict__ fach,
                const int* __restrict__ start,
                const int* __restrict__ colS,
                float* __restrict__ out) {
    const int lane = threadIdx.x & 31;
    const int n = (blockIdx.x * blockDim.x + threadIdx.x) >> 5;
    if (n >= NNODES) return;

    const size_t base = (size_t)n * DIM;
    float4 h = __ldg((const float4*)(head_src + base) + lane);
    int s     = __ldg(start + n);
    int e_end = __ldg(start + n + 1);

    const uint2* th = (const uint2*)fach;   // 32 uint2 (8 halves... 4 halves) per node row

    float4 acc = make_float4(0.f, 0.f, 0.f, 0.f);

    uint2 t0 = make_uint2(0u, 0u), t1 = make_uint2(0u, 0u);
    if (s < e_end) {
        int c = __ldg(colS + s);
        t0 = __ldg(th + (size_t)c * 32 + lane);
    }
    if (s + 1 < e_end) {
        int c = __ldg(colS + s + 1);
        t1 = __ldg(th + (size_t)c * 32 + lane);
    }

    for (int e = s; e < e_end; e++) {
        uint2 cur = t0;
        t0 = t1;
        if (e + 2 < e_end) {
            int c = __ldg(colS + e + 2);
            t1 = __ldg(th + (size_t)c * 32 + lane);
        }
        __half2 h0 = *(__half2*)&cur.x;
        __half2 h1 = *(__half2*)&cur.y;
        float2 f0 = __half22float2(h0);
        float2 f1 = __half22float2(h1);

        float dp = h.x*f0.x + h.y*f0.y + h.z*f1.x + h.w*f1.y;
        dp += __shfl_xor_sync(0xFFFFFFFFu, dp, 1);
        dp += __shfl_xor_sync(0xFFFFFFFFu, dp, 2);
        dp += __shfl_xor_sync(0xFFFFFFFFu, dp, 4);
        // dots of unit vectors are in [-1,1] -> no max-subtraction needed
        float ea = __expf(dp);
        float eb = __shfl_xor_sync(0xFFFFFFFFu, ea, 8);
        float ec = __shfl_xor_sync(0xFFFFFFFFu, ea, 16);
        float ed = __shfl_xor_sync(0xFFFFFFFFu, eb, 16);
        float p  = ea / (ea + eb + ec + ed);
        acc.x += p * f0.x; acc.y += p * f0.y;
        acc.z += p * f1.x; acc.w += p * f1.y;
    }

    // residual base is ALWAYS the original fac (both iterations), fp32-exact
    float4 f = (head_src == fac) ? h : __ldg((const float4*)(fac + base) + lane);
    float4 v = make_float4(f.x + acc.x, f.y + acc.y, f.z + acc.z, f.w + acc.w);
    float ss = v.x*v.x + v.y*v.y + v.z*v.z + v.w*v.w;
    ss += __shfl_xor_sync(0xFFFFFFFFu, ss, 1);
    ss += __shfl_xor_sync(0xFFFFFFFFu, ss, 2);
    ss += __shfl_xor_sync(0xFFFFFFFFu, ss, 4);
    float inv = 1.0f / fmaxf(sqrtf(ss), 1e-12f);
    v.x *= inv; v.y *= inv; v.z *= inv; v.w *= inv;
    ((float4*)(out + base))[lane] = v;
}

// ---------------------------------------------------------------------------
extern "C" void kernel_launch(void* const* d_in, const int* in_sizes, int n_in,
                              void* d_out, int out_size) {
    const float* all_emb = (const float*)d_in[0];
    const float* W       = (const float*)d_in[1];
    const float* b       = (const float*)d_in[2];
    const int*   row     = (const int*)  d_in[3];
    const int*   col     = (const int*)  d_in[4];
    int          E       = in_sizes[3];
    if (E > EMAX) E = EMAX;
    float*       out     = (float*)d_out;

    float *fac, *nf;
    __half* fach;
    int *deg, *start, *cursor, *colS, *bsums, *boffs;
    cudaGetSymbolAddress((void**)&fac,    g_fac);
    cudaGetSymbolAddress((void**)&nf,     g_new);
    cudaGetSymbolAddress((void**)&fach,   g_fach);
    cudaGetSymbolAddress((void**)&deg,    g_deg);
    cudaGetSymbolAddress((void**)&start,  g_start);
    cudaGetSymbolAddress((void**)&cursor, g_cursor);
    cudaGetSymbolAddress((void**)&colS,   g_colS);
    cudaGetSymbolAddress((void**)&bsums,  g_bsums);
    cudaGetSymbolAddress((void**)&boffs,  g_boffs);

    const int smem = (DIM * DIM + 64 * DIM) * sizeof(float);  // 96 KB
    cudaFuncSetAttribute(gemm_kernel, cudaFuncAttributeMaxDynamicSharedMemorySize, smem);

    // Phase 1: factor embeddings (fp32x2 packed FMA) + fp16 tail table
    gemm_kernel<<<1563, 256, smem>>>(all_emb, W, b, fac, fach);

    // Phase 2: CSR build (row/col identical for both iterations -> build once)
    zero_deg_kernel<<<(NNODES + 255) / 256, 256>>>(deg);
    hist_kernel<<<2048, 256>>>(row, E, deg);
    scan_partial_kernel<<<SCAN_NBLK, 256>>>(deg, bsums);
    scan_sums_kernel<<<1, 64>>>(bsums, boffs, start);
    scan_final_kernel<<<SCAN_NBLK, 256>>>(deg, boffs, start, cursor);
    scatter_kernel<<<2048, 256>>>(row, col, E, cursor, colS);

    // Phase 3: two fused propagate+norm iterations (warp per node)
    const int blocks = (NNODES * 32 + 255) / 256;   // 12500
    fused_edge_norm<<<blocks, 256>>>(fac, fac, fach, start, colS, nf);
    fused_edge_norm<<<blocks, 256>>>(nf,  fac, fach, start, colS, out);
}

// round 14
// speedup vs baseline: 2.9793x; 1.0677x over previous
#include <cuda_runtime.h>
#include <cuda_fp16.h>
#include <cuda_bf16.h>
#include <cstdint>

// Problem constants (fixed by the reference generator)
#define NNODES 100000
#define DIM    128          // FAC_K * DIM_K = 4 * 32
#define FAC_K  4
#define DIM_K  32
#define EMAX   1600000

#define SCAN_CHUNK 2048
#define SCAN_NBLK  ((NNODES + SCAN_CHUNK - 1) / SCAN_CHUNK)   // 49

// Scratch (node-major: fac[n*128 + f*32 + k])
__device__ float  g_fac[(size_t)NNODES * DIM];
__device__ float  g_new[(size_t)NNODES * DIM];
__device__ __half g_fach[(size_t)NNODES * DIM];   // fp16 copy of fac for gathers
__device__ int    g_deg[NNODES];
__device__ int    g_start[NNODES + 1];
__device__ int    g_cursor[NNODES];
__device__ int    g_colS[EMAX];
__device__ int    g_bsums[64];
__device__ int    g_boffs[64];

// ---------------------------------------------------------------------------
// Blackwell packed fp32 helpers (double-rate FFMA2 — exact fp32 semantics)
// ---------------------------------------------------------------------------
__device__ __forceinline__ unsigned long long pk2(float lo, float hi) {
    unsigned long long r;
    asm("mov.b64 %0, {%1, %2};" : "=l"(r) : "f"(lo), "f"(hi));
    return r;
}
__device__ __forceinline__ void fma2(unsigned long long& d,
                                     unsigned long long a, unsigned long long b) {
    asm("fma.rn.f32x2 %0, %1, %2, %0;" : "+l"(d) : "l"(a), "l"(b));
}
__device__ __forceinline__ void upk2(unsigned long long v, float& lo, float& hi) {
    asm("mov.b64 {%0, %1}, %2;" : "=f"(lo), "=f"(hi) : "l"(v));
}

// ---------------------------------------------------------------------------
// GEMM + leakyReLU + per-factor L2 norm.  fp32x2 packed FMA mainloop.
// Writes fac (fp32) and fac_h (fp16 tail table).
// ---------------------------------------------------------------------------
__global__ void __launch_bounds__(256, 2)
gemm_kernel(const float* __restrict__ emb, const float* __restrict__ W,
            const float* __restrict__ b, float* __restrict__ fac,
            __half* __restrict__ fach) {
    extern __shared__ float sm[];
    float* sW = sm;               // 128*128 floats
    float* sA = sm + DIM * DIM;   // 64*128 floats

    const int tid  = threadIdx.x;
    const int lane = tid & 31;
    const int w    = tid >> 5;

    // W'[d][c] = W[f][d][k] + b[f][k],  c = f*32+k
    for (int i = tid; i < DIM * DIM; i += 256) {
        int d = i >> 7, c = i & 127;
        int f = c >> 5, k = c & 31;
        sW[i] = W[(f * DIM + d) * DIM_K + k] + b[f * DIM_K + k];
    }
    __syncthreads();

    const float4* sW4 = (const float4*)sW;
    const int TILE = 64;

    for (int base = blockIdx.x * TILE; base < NNODES; base += gridDim.x * TILE) {
        int rows = NNODES - base; if (rows > TILE) rows = TILE;
        __syncthreads();
        const float4* src = (const float4*)(emb + (size_t)base * DIM);
        float4* dstA = (float4*)sA;
        for (int i = tid; i < rows * (DIM / 4); i += 256) dstA[i] = src[i];
        __syncthreads();

        unsigned long long axy[8], azw[8];
        #pragma unroll
        for (int r = 0; r < 8; r++) { axy[r] = pk2(0.f, 0.f); azw[r] = pk2(0.f, 0.f); }

        #pragma unroll 2
        for (int d0 = 0; d0 < DIM; d0 += 4) {
            unsigned long long wxy[4], wzw[4];
            #pragma unroll
            for (int i = 0; i < 4; i++) {
                float4 w4 = sW4[(d0 + i) * 32 + lane];
                wxy[i] = pk2(w4.x, w4.y);
                wzw[i] = pk2(w4.z, w4.w);
            }
            #pragma unroll
            for (int r = 0; r < 8; r++) {
                float4 a4 = *(const float4*)&sA[(w * 8 + r) * DIM + d0];
                unsigned long long aa;
                aa = pk2(a4.x, a4.x); fma2(axy[r], aa, wxy[0]); fma2(azw[r], aa, wzw[0]);
                aa = pk2(a4.y, a4.y); fma2(axy[r], aa, wxy[1]); fma2(azw[r], aa, wzw[1]);
                aa = pk2(a4.z, a4.z); fma2(axy[r], aa, wxy[2]); fma2(azw[r], aa, wzw[2]);
                aa = pk2(a4.w, a4.w); fma2(axy[r], aa, wxy[3]); fma2(azw[r], aa, wzw[3]);
            }
        }

        #pragma unroll
        for (int r = 0; r < 8; r++) {
            int gr = base + w * 8 + r;
            if (gr >= NNODES) break;
            float4 v;
            upk2(axy[r], v.x, v.y);
            upk2(azw[r], v.z, v.w);
            v.x = v.x > 0.f ? v.x : 0.2f * v.x;
            v.y = v.y > 0.f ? v.y : 0.2f * v.y;
            v.z = v.z > 0.f ? v.z : 0.2f * v.z;
            v.w = v.w > 0.f ? v.w : 0.2f * v.w;
            float s = v.x*v.x + v.y*v.y + v.z*v.z + v.w*v.w;
            s += __shfl_xor_sync(0xFFFFFFFFu, s, 1);
            s += __shfl_xor_sync(0xFFFFFFFFu, s, 2);
            s += __shfl_xor_sync(0xFFFFFFFFu, s, 4);   // 8-lane group = one factor
            float inv = 1.0f / fmaxf(sqrtf(s), 1e-12f);
            v.x *= inv; v.y *= inv; v.z *= inv; v.w *= inv;
            ((float4*)(fac + (size_t)gr * DIM))[lane] = v;
            __half2 h0 = __floats2half2_rn(v.x, v.y);
            __half2 h1 = __floats2half2_rn(v.z, v.w);
            uint2 u;
            u.x = *(unsigned int*)&h0;
            u.y = *(unsigned int*)&h1;
            ((uint2*)fach)[(size_t)gr * 32 + lane] = u;
        }
    }
}

// ---------------------------------------------------------------------------
// CSR build: histogram -> 3-phase multi-block scan -> scatter of col ids.
// ---------------------------------------------------------------------------
__global__ void zero_deg_kernel(int* __restrict__ deg) {
    int i = blockIdx.x * blockDim.x + threadIdx.x;
    if (i < NNODES) deg[i] = 0;
}

__global__ void hist_kernel(const int* __restrict__ row, int E, int* __restrict__ deg) {
    for (int e = blockIdx.x * blockDim.x + threadIdx.x; e < E; e += gridDim.x * blockDim.x)
        atomicAdd(&deg[row[e]], 1);
}

__global__ void __launch_bounds__(256)
scan_partial_kernel(const int* __restrict__ deg, int* __restrict__ bsums) {
    const int tid  = threadIdx.x;
    const int lane = tid & 31;
    const int wid  = tid >> 5;
    const int base = blockIdx.x * SCAN_CHUNK;
    int s = 0;
    #pragma unroll
    for (int k = 0; k < SCAN_CHUNK / 256; k++) {
        int idx = base + tid + k * 256;
        if (idx < NNODES) s += deg[idx];
    }
    s += __shfl_down_sync(0xFFFFFFFFu, s, 16);
    s += __shfl_down_sync(0xFFFFFFFFu, s, 8);
    s += __shfl_down_sync(0xFFFFFFFFu, s, 4);
    s += __shfl_down_sync(0xFFFFFFFFu, s, 2);
    s += __shfl_down_sync(0xFFFFFFFFu, s, 1);
    __shared__ int ws[8];
    if (lane == 0) ws[wid] = s;
    __syncthreads();
    if (wid == 0) {
        int v = (lane < 8) ? ws[lane] : 0;
        v += __shfl_down_sync(0xFFFFFFFFu, v, 4);
        v += __shfl_down_sync(0xFFFFFFFFu, v, 2);
        v += __shfl_down_sync(0xFFFFFFFFu, v, 1);
        if (lane == 0) bsums[blockIdx.x] = v;
    }
}

__global__ void scan_sums_kernel(const int* __restrict__ bsums, int* __restrict__ boffs,
                                 int* __restrict__ start) {
    __shared__ int buf[64];
    int tid = threadIdx.x;                         // 64 threads
    int v = (tid < SCAN_NBLK) ? bsums[tid] : 0;
    buf[tid] = v;
    __syncthreads();
    #pragma unroll
    for (int off = 1; off < 64; off <<= 1) {
        int u = (tid >= off) ? buf[tid - off] : 0;
        __syncthreads();
        buf[tid] += u;
        __syncthreads();
    }
    if (tid < SCAN_NBLK) boffs[tid] = buf[tid] - v;   // exclusive
    if (tid == 63) start[NNODES] = buf[63];           // total edge count
}

__global__ void __launch_bounds__(256)
scan_final_kernel(const int* __restrict__ deg, const int* __restrict__ boffs,
                  int* __restrict__ start, int* __restrict__ cursor) {
    const int tid  = threadIdx.x;
    const int lane = tid & 31;
    const int wid  = tid >> 5;
    const int base = blockIdx.x * SCAN_CHUNK + tid * 8;

    int v[8];
    #pragma unroll
    for (int j = 0; j < 8; j++) {
        int idx = base + j;
        v[j] = (idx < NNODES) ? deg[idx] : 0;
    }
    int tsum = 0;
    #pragma unroll
    for (int j = 0; j < 8; j++) { int x = v[j]; v[j] = tsum; tsum += x; }

    int inc = tsum;
    #pragma unroll
    for (int off = 1; off < 32; off <<= 1) {
        int u = __shfl_up_sync(0xFFFFFFFFu, inc, off);
        if (lane >= off) inc += u;
    }
    int wexcl = inc - tsum;

    __shared__ int ws[8], wo[8];
    if (lane == 31) ws[wid] = inc;
    __syncthreads();
    if (tid < 8) {
        int e = 0;
        for (int k = 0; k < tid; k++) e += ws[k];
        wo[tid] = e;
    }
    __syncthreads();

    int off0 = boffs[blockIdx.x] + wo[wid] + wexcl;
    #pragma unroll
    for (int j = 0; j < 8; j++) {
        int idx = base + j;
        if (idx < NNODES) {
            int e = off0 + v[j];
            start[idx]  = e;
            cursor[idx] = e;
        }
    }
}

__global__ void scatter_kernel(const int* __restrict__ row, const int* __restrict__ col,
                               int E, int* __restrict__ cursor, int* __restrict__ colS) {
    for (int e = blockIdx.x * blockDim.x + threadIdx.x; e < E; e += gridDim.x * blockDim.x) {
        int r = row[e];
        int pos = atomicAdd(&cursor[r], 1);
        colS[pos] = col[e];
    }
}

// ---------------------------------------------------------------------------
// Fused per-iteration kernel: one warp per destination node.
// 4-edge batched inner loop: 4 INDEPENDENT dot/softmax shfl chains overlap
// (the serial 200-cyc per-edge chain was the R12 bottleneck), plus 4-deep
// tail-gather prefetch (MLP 4). Softmax sum uses 2 shfls (pairwise).
// ---------------------------------------------------------------------------
__global__ void __launch_bounds__(256)
fused_edge_norm(const float* __restrict__ head_src,
                const float* __restrict__ fac,
                const __half* __restrict__ fach,
                const int* __restrict__ start,
                const int* __restrict__ colS,
                float* __restrict__ out) {
    const int lane = threadIdx.x & 31;
    const int n = (blockIdx.x * blockDim.x + threadIdx.x) >> 5;
    if (n >= NNODES) return;

    const size_t base = (size_t)n * DIM;
    float4 h = __ldg((const float4*)(head_src + base) + lane);
    int s     = __ldg(start + n);
    int e_end = __ldg(start + n + 1);

    const uint2* th = (const uint2*)fach;

    float4 acc = make_float4(0.f, 0.f, 0.f, 0.f);

    uint2 cur[4], nxt[4];
    {
        int nb = e_end - s; if (nb > 4) nb = 4;
        #pragma unroll
        for (int j = 0; j < 4; j++)
            if (j < nb) {
                int c = __ldg(colS + s + j);
                cur[j] = __ldg(th + (size_t)c * 32 + lane);
            }
    }

    int e = s;
    while (e + 4 <= e_end) {
        // prefetch next batch
        int rem = e_end - (e + 4); if (rem > 4) rem = 4;
        #pragma unroll
        for (int j = 0; j < 4; j++)
            if (j < rem) {
                int c = __ldg(colS + e + 4 + j);
                nxt[j] = __ldg(th + (size_t)c * 32 + lane);
            }

        // 4 independent edge chains
        float2 f0[4], f1[4];
        float dp[4];
        #pragma unroll
        for (int j = 0; j < 4; j++) {
            f0[j] = __half22float2(*(__half2*)&cur[j].x);
            f1[j] = __half22float2(*(__half2*)&cur[j].y);
            dp[j] = h.x*f0[j].x + h.y*f0[j].y + h.z*f1[j].x + h.w*f1[j].y;
        }
        #pragma unroll
        for (int j = 0; j < 4; j++) dp[j] += __shfl_xor_sync(0xFFFFFFFFu, dp[j], 1);
        #pragma unroll
        for (int j = 0; j < 4; j++) dp[j] += __shfl_xor_sync(0xFFFFFFFFu, dp[j], 2);
        #pragma unroll
        for (int j = 0; j < 4; j++) dp[j] += __shfl_xor_sync(0xFFFFFFFFu, dp[j], 4);
        float ea[4], s1[4], st[4];
        #pragma unroll
        for (int j = 0; j < 4; j++) ea[j] = __expf(dp[j]);
        #pragma unroll
        for (int j = 0; j < 4; j++) s1[j] = ea[j] + __shfl_xor_sync(0xFFFFFFFFu, ea[j], 8);
        #pragma unroll
        for (int j = 0; j < 4; j++) st[j] = s1[j] + __shfl_xor_sync(0xFFFFFFFFu, s1[j], 16);
        #pragma unroll
        for (int j = 0; j < 4; j++) {
            float p = ea[j] / st[j];
            acc.x += p * f0[j].x; acc.y += p * f0[j].y;
            acc.z += p * f1[j].x; acc.w += p * f1[j].y;
        }

        #pragma unroll
        for (int j = 0; j < 4; j++) cur[j] = nxt[j];
        e += 4;
    }

    // remainder (0..3 edges, already in cur[])
    int rem = e_end - e;
    #pragma unroll
    for (int j = 0; j < 3; j++) {
        if (j < rem) {
            float2 f0 = __half22float2(*(__half2*)&cur[j].x);
            float2 f1 = __half22float2(*(__half2*)&cur[j].y);
            float dp = h.x*f0.x + h.y*f0.y + h.z*f1.x + h.w*f1.y;
            dp += __shfl_xor_sync(0xFFFFFFFFu, dp, 1);
            dp += __shfl_xor_sync(0xFFFFFFFFu, dp, 2);
            dp += __shfl_xor_sync(0xFFFFFFFFu, dp, 4);
            float ea = __expf(dp);
            float s1 = ea + __shfl_xor_sync(0xFFFFFFFFu, ea, 8);
            float st = s1 + __shfl_xor_sync(0xFFFFFFFFu, s1, 16);
            float p  = ea / st;
            acc.x += p * f0.x; acc.y += p * f0.y;
            acc.z += p * f1.x; acc.w += p * f1.y;
        }
    }

    // residual base is ALWAYS the original fac (both iterations), fp32-exact
    float4 f = (head_src == fac) ? h : __ldg((const float4*)(fac + base) + lane);
    float4 v = make_float4(f.x + acc.x, f.y + acc.y, f.z + acc.z, f.w + acc.w);
    float ss = v.x*v.x + v.y*v.y + v.z*v.z + v.w*v.w;
    ss += __shfl_xor_sync(0xFFFFFFFFu, ss, 1);
    ss += __shfl_xor_sync(0xFFFFFFFFu, ss, 2);
    ss += __shfl_xor_sync(0xFFFFFFFFu, ss, 4);
    float inv = 1.0f / fmaxf(sqrtf(ss), 1e-12f);
    v.x *= inv; v.y *= inv; v.z *= inv; v.w *= inv;
    ((float4*)(out + base))[lane] = v;
}

// ---------------------------------------------------------------------------
extern "C" void kernel_launch(void* const* d_in, const int* in_sizes, int n_in,
                              void* d_out, int out_size) {
    const float* all_emb = (const float*)d_in[0];
    const float* W       = (const float*)d_in[1];
    const float* b       = (const float*)d_in[2];
    const int*   row     = (const int*)  d_in[3];
    const int*   col     = (const int*)  d_in[4];
    int          E       = in_sizes[3];
    if (E > EMAX) E = EMAX;
    float*       out     = (float*)d_out;

    float *fac, *nf;
    __half* fach;
    int *deg, *start, *cursor, *colS, *bsums, *boffs;
    cudaGetSymbolAddress((void**)&fac,    g_fac);
    cudaGetSymbolAddress((void**)&nf,     g_new);
    cudaGetSymbolAddress((void**)&fach,   g_fach);
    cudaGetSymbolAddress((void**)&deg,    g_deg);
    cudaGetSymbolAddress((void**)&start,  g_start);
    cudaGetSymbolAddress((void**)&cursor, g_cursor);
    cudaGetSymbolAddress((void**)&colS,   g_colS);
    cudaGetSymbolAddress((void**)&bsums,  g_bsums);
    cudaGetSymbolAddress((void**)&boffs,  g_boffs);

    const int smem = (DIM * DIM + 64 * DIM) * sizeof(float);  // 96 KB
    cudaFuncSetAttribute(gemm_kernel, cudaFuncAttributeMaxDynamicSharedMemorySize, smem);

    // Phase 1: factor embeddings (fp32x2 packed FMA) + fp16 tail table
    gemm_kernel<<<1563, 256, smem>>>(all_emb, W, b, fac, fach);

    // Phase 2: CSR build (row/col identical for both iterations -> build once)
    zero_deg_kernel<<<(NNODES + 255) / 256, 256>>>(deg);
    hist_kernel<<<2048, 256>>>(row, E, deg);
    scan_partial_kernel<<<SCAN_NBLK, 256>>>(deg, bsums);
    scan_sums_kernel<<<1, 64>>>(bsums, boffs, start);
    scan_final_kernel<<<SCAN_NBLK, 256>>>(deg, boffs, start, cursor);
    scatter_kernel<<<2048, 256>>>(row, col, E, cursor, colS);

    // Phase 3: two fused propagate+norm iterations (warp per node)
    const int blocks = (NNODES * 32 + 255) / 256;   // 12500
    fused_edge_norm<<<blocks, 256>>>(fac, fac, fach, start, colS, nf);
    fused_edge_norm<<<blocks, 256>>>(nf,  fac, fach, start, colS, out);
}